// round 8
// baseline (speedup 1.0000x reference)
#include <cuda_runtime.h>
#include <math.h>
#include <stdint.h>

// EntropyLoss: x [R=65536, C=1024] f32 row-major.
//   n_j  = max( sqrt(sum_i x_ij^2), 1e-12 )
//   out  = -(1/R) * sum_j (1/n_j) * [ sum_i x*ln(x) - ln(n_j) * sum_i x ]
// (eps=1e-8 inside the reference log contributes <1e-6 relative error; dropped)
//
// R8: cp.async.bulk (TMA-path) smem pipeline. R5-R7 showed the LDG-path
// plateaus at ~5.7-5.9 TB/s regardless of occupancy / MLP / load balance, so
// this round decouples loads from compute: a producer warp streams 32KB
// stages (8 contiguous rows) into a 3-deep smem ring via
// cp.async.bulk.mbarrier::complete_tx; 8 consumer warps (256 threads) each
// own 4 fixed columns and accumulate from smem (conflict-free LDS.128).
// No intra-CTA column reduction needed. Last CTA combines -> scalar and
// re-zeros all scratch for the next graph replay.

#define COLS 1024
#define NCTAS 296                 // 2 CTAs/SM, one wave
#define STAGE_ROWS 8
#define STAGE_FLOATS (STAGE_ROWS * COLS)   // 8192
#define STAGE_BYTES  (STAGE_FLOATS * 4)    // 32768
#define NSLOTS 3
#define SMEM_BYTES (128 + NSLOTS * STAGE_BYTES)   // 98432
#define LN2 0.6931471805599453f

__device__ float g_part[3][COLS];   // [0]=sum x^2, [1]=sum x, [2]=sum x*log2(x)
__device__ unsigned int g_count;

__device__ __forceinline__ uint32_t smem_u32(const void* p) {
    uint32_t a;
    asm("{ .reg .u64 t; cvta.to.shared.u64 t, %1; cvt.u32.u64 %0, t; }"
        : "=r"(a) : "l"(p));
    return a;
}
__device__ __forceinline__ void mbar_init(uint32_t a, uint32_t n) {
    asm volatile("mbarrier.init.shared.b64 [%0], %1;" :: "r"(a), "r"(n) : "memory");
}
__device__ __forceinline__ void mbar_expect_tx(uint32_t a, uint32_t bytes) {
    asm volatile("mbarrier.arrive.expect_tx.shared.b64 _, [%0], %1;"
                 :: "r"(a), "r"(bytes) : "memory");
}
__device__ __forceinline__ void mbar_arrive(uint32_t a) {
    asm volatile("mbarrier.arrive.shared.b64 _, [%0];" :: "r"(a) : "memory");
}
__device__ __forceinline__ void mbar_wait(uint32_t a, uint32_t ph) {  // acquire
    uint32_t done;
    asm volatile(
        "{\n\t.reg .pred p;\n\t"
        "mbarrier.try_wait.parity.acquire.cta.shared::cta.b64 p, [%1], %2;\n\t"
        "selp.b32 %0, 1, 0, p;\n\t}"
        : "=r"(done) : "r"(a), "r"(ph) : "memory");
    if (!done) {
        asm volatile(
            "{\n\t.reg .pred P1;\n\t"
            "W_%=:\n\t"
            "mbarrier.try_wait.parity.acquire.cta.shared::cta.b64 P1, [%0], %1, 0x989680;\n\t"
            "@P1 bra.uni D_%=;\n\t"
            "bra.uni W_%=;\n\t"
            "D_%=:\n\t}"
            :: "r"(a), "r"(ph) : "memory");
    }
}
__device__ __forceinline__ void bulk_copy(uint32_t dst, const void* src,
                                          uint32_t bytes, uint32_t mbar) {
    asm volatile(
        "cp.async.bulk.shared::cluster.global.mbarrier::complete_tx::bytes "
        "[%0], [%1], %2, [%3];"
        :: "r"(dst), "l"(src), "r"(bytes), "r"(mbar) : "memory");
}

__global__ __launch_bounds__(288, 2) void el_pipe_kernel(const float* __restrict__ x,
                                                         float* __restrict__ out,
                                                         int rows) {
    extern __shared__ unsigned char smem_raw[];
    // bytes [0,48): 3 x (full, empty) mbarrier pairs (16B stride per slot)
    // bytes [128, 128+3*32768): stage buffers
    float* buf = (float*)(smem_raw + 128);
    const uint32_t bar0 = smem_u32(smem_raw);
    const uint32_t buf0 = smem_u32(buf);

    const int tid = threadIdx.x;
    const int b   = blockIdx.x;
    const int nstages = rows >> 3;                         // 8192
    const int n_my    = (nstages - b + NCTAS - 1) / NCTAS; // 27 or 28

    if (tid == 0) {
        #pragma unroll
        for (int s = 0; s < NSLOTS; s++) {
            mbar_init(bar0 + s * 16,     1);    // full: producer expect_tx arrive
            mbar_init(bar0 + s * 16 + 8, 256);  // empty: all consumer threads
        }
    }
    __syncthreads();

    float s2[4] = {0.f, 0.f, 0.f, 0.f};
    float s1[4] = {0.f, 0.f, 0.f, 0.f};
    float sx[4] = {0.f, 0.f, 0.f, 0.f};

    if (tid == 256) {
        // -------- producer (single thread of warp 8) --------
        int slot = 0, ph = 1;   // phase=1: first empty-wait passes immediately
        for (int i = 0; i < n_my; i++) {
            mbar_wait(bar0 + slot * 16 + 8, (uint32_t)ph);       // empty
            uint32_t fb = bar0 + slot * 16;
            mbar_expect_tx(fb, STAGE_BYTES);
            const float* src = x + (long)(b + (long)i * NCTAS) * STAGE_FLOATS;
            bulk_copy(buf0 + slot * STAGE_BYTES, src, STAGE_BYTES, fb);
            if (++slot == NSLOTS) { slot = 0; ph ^= 1; }
        }
    } else if (tid < 256) {
        // -------- consumers: thread t owns columns 4t..4t+3 --------
        int slot = 0, ph = 0;
        for (int i = 0; i < n_my; i++) {
            mbar_wait(bar0 + slot * 16, (uint32_t)ph);           // full (acquire)
            const float* bp = buf + slot * STAGE_FLOATS + 4 * tid;
            #pragma unroll
            for (int rr = 0; rr < STAGE_ROWS; rr++) {
                float4 v = *(const float4*)(bp + rr * COLS);
                float vv[4] = {v.x, v.y, v.z, v.w};
                #pragma unroll
                for (int k = 0; k < 4; k++) {
                    float a = vv[k];
                    s2[k] = fmaf(a, a, s2[k]);
                    s1[k] += a;
                    // x*log2(x): at a==0 -> fmaf(0, lg2(1e-37), s) == s
                    float l = __log2f(fmaxf(a, 1e-37f));
                    sx[k] = fmaf(a, l, sx[k]);
                }
            }
            mbar_arrive(bar0 + slot * 16 + 8);                   // empty
            if (++slot == NSLOTS) { slot = 0; ph ^= 1; }
        }
        // remainder rows (rows % 8 != 0; dead for this shape) — block 0 only
        if (b == 0) {
            for (int r = nstages * STAGE_ROWS; r < rows; r++) {
                float4 v = ((const float4*)x)[(long)r * (COLS / 4) + tid];
                float vv[4] = {v.x, v.y, v.z, v.w};
                #pragma unroll
                for (int k = 0; k < 4; k++) {
                    float a = vv[k];
                    s2[k] = fmaf(a, a, s2[k]);
                    s1[k] += a;
                    float l = __log2f(fmaxf(a, 1e-37f));
                    sx[k] = fmaf(a, l, sx[k]);
                }
            }
        }
        // per-thread columns are exclusive within the CTA: atomics directly
        #pragma unroll
        for (int k = 0; k < 4; k++) {
            atomicAdd(&g_part[0][4 * tid + k], s2[k]);
            atomicAdd(&g_part[1][4 * tid + k], s1[k]);
            atomicAdd(&g_part[2][4 * tid + k], sx[k]);
        }
    }

    // ---- last CTA does the final combine ----
    __shared__ int amLast;
    __threadfence();
    __syncthreads();
    if (tid == 0) {
        unsigned v = atomicAdd(&g_count, 1u);
        amLast = (v == NCTAS - 1);
    }
    __syncthreads();
    if (!amLast) return;

    float acc = 0.f;
    if (tid < 256) {
        #pragma unroll
        for (int m = 0; m < 4; m++) {
            int j = tid + m * 256;
            float S2 = __ldcg(&g_part[0][j]);
            float S1 = __ldcg(&g_part[1][j]);
            float SX = __ldcg(&g_part[2][j]);
            float n  = fmaxf(sqrtf(S2), 1e-12f);
            acc += (SX * LN2 - S1 * logf(n)) / n;
        }
    }
    __syncthreads();   // all reads of g_part done before re-zero
    for (int i = tid; i < 3 * COLS; i += 288) ((float*)g_part)[i] = 0.0f;
    if (tid == 0) g_count = 0u;

    __shared__ float sm[256];
    if (tid < 256) sm[tid] = acc;
    __syncthreads();
    #pragma unroll
    for (int s = 128; s > 0; s >>= 1) {
        if (tid < s) sm[tid] += sm[tid + s];
        __syncthreads();
    }
    if (tid == 0) out[0] = -sm[0] / (float)rows;
}

extern "C" void kernel_launch(void* const* d_in, const int* in_sizes, int n_in,
                              void* d_out, int out_size) {
    const float* x = (const float*)d_in[0];
    int rows = in_sizes[0] / COLS;   // 65536
    cudaFuncSetAttribute(el_pipe_kernel,
                         cudaFuncAttributeMaxDynamicSharedMemorySize, SMEM_BYTES);
    el_pipe_kernel<<<NCTAS, 288, SMEM_BYTES>>>(x, (float*)d_out, rows);
}

// round 9
// speedup vs baseline: 1.2140x; 1.2140x over previous
#include <cuda_runtime.h>
#include <math.h>

// EntropyLoss: x [R=65536, C=1024] f32 row-major.
//   n_j  = max( sqrt(sum_i x_ij^2), 1e-12 )
//   out  = -(1/R) * sum_j (1/n_j) * [ sum_i x*ln(x) - ln(n_j) * sum_i x ]
// (eps=1e-8 inside the reference log contributes <1e-6 relative error; dropped)
//
// R9 = R6 (best: 47.6us, DRAM 74.8%) + __ldcs evict-first hints on the
// 256MB read-once stream (single-variable change; R4's __ldcs test was
// confounded with a bad manual-batching rewrite). TMA pipeline (R8) and
// work-stealing (R7) were tried and regressed/neutral - LDG @ 40 warps/SM
// with fixed-8 front-batched loads is the validated feed mechanism.
//
// Single fused launch, one wave of 740 CTAs (5/SM). __launch_bounds__(256,5)
// gives the ~48-reg budget ptxas needs to front-batch the 8 independent
// float4 loads. Last block combines columns -> scalar, writes out, re-zeros
// scratch so every graph replay starts clean.

#define COLS 1024
#define GRID_X 185          // 185*4 = 740 CTAs = 5/SM, one wave
#define GRID_Y 4            // column tiles of 256
#define NBLOCKS (GRID_X * GRID_Y)
#define LN2 0.6931471805599453f

__device__ float g_part[3][COLS];      // [0]=sum x^2, [1]=sum x, [2]=sum x*log2(x)
__device__ unsigned int g_count;

__global__ __launch_bounds__(256, 5) void el_fused_kernel(const float* __restrict__ x,
                                                          float* __restrict__ out,
                                                          int rows) {
    const int tid     = threadIdx.x;
    const int cg      = tid & 63;     // 64 float4 column-groups per block (256 cols)
    const int slice   = tid >> 6;     // 4 row slices per block
    const int colbase = blockIdx.y * 256;
    const int g4      = (colbase >> 2) + cg;   // float4 index within a row

    const float4* __restrict__ p = (const float4*)x;

    float s2[4] = {0.f, 0.f, 0.f, 0.f};
    float s1[4] = {0.f, 0.f, 0.f, 0.f};
    float sx[4] = {0.f, 0.f, 0.f, 0.f};

    const int  rstride = GRID_X * 4;                 // 740 row slices total
    const int  r0      = blockIdx.x * 4 + slice;
    const long step    = (long)rstride * (COLS / 4);
    const float4* __restrict__ q = p + (long)r0 * (COLS / 4) + g4;

    const int iters = (rows - r0 + rstride - 1) / rstride;   // ~88-89
    const int it8   = iters & ~7;

    for (int b = 0; b < it8; b += 8) {
        // fixed trip count of 8: ptxas fully unrolls and front-batches the
        // 8 independent float4 loads; .cs = evict-first (read-once stream)
        #pragma unroll
        for (int u = 0; u < 8; u++) {
            float4 v = __ldcs(&q[(long)u * step]);
            float vv[4] = {v.x, v.y, v.z, v.w};
            #pragma unroll
            for (int k = 0; k < 4; k++) {
                float a = vv[k];
                s2[k] = fmaf(a, a, s2[k]);
                s1[k] += a;
                // x*log2(x): at a==0 this is fmaf(0, lg2(1e-37), s) == s
                float l = __log2f(fmaxf(a, 1e-37f));
                sx[k] = fmaf(a, l, sx[k]);
            }
        }
        q += 8 * step;
    }
    for (int i = it8; i < iters; i++) {
        float4 v = __ldcs(q);
        q += step;
        float vv[4] = {v.x, v.y, v.z, v.w};
        #pragma unroll
        for (int k = 0; k < 4; k++) {
            float a = vv[k];
            s2[k] = fmaf(a, a, s2[k]);
            s1[k] += a;
            float l = __log2f(fmaxf(a, 1e-37f));
            sx[k] = fmaf(a, l, sx[k]);
        }
    }

    // Reduce the 4 row-slices within the block before touching L2 atomics.
    __shared__ float red[4][64 * 12];
    #pragma unroll
    for (int k = 0; k < 4; k++) {
        red[slice][cg * 12 + 0 + k] = s2[k];
        red[slice][cg * 12 + 4 + k] = s1[k];
        red[slice][cg * 12 + 8 + k] = sx[k];
    }
    __syncthreads();

    for (int i = tid; i < 64 * 12; i += 256) {
        float t = red[0][i] + red[1][i] + red[2][i] + red[3][i];
        int cg2  = i / 12;
        int comp = i % 12;
        int type = comp >> 2;     // 0: x^2, 1: x, 2: x*log2(x)
        int sub  = comp & 3;
        int col  = colbase + cg2 * 4 + sub;
        atomicAdd(&g_part[type][col], t);
    }

    // ---- last block does the final combine ----
    __shared__ int amLast;
    __threadfence();
    __syncthreads();
    if (tid == 0) {
        unsigned v = atomicAdd(&g_count, 1u);
        amLast = (v == NBLOCKS - 1);
    }
    __syncthreads();
    if (!amLast) return;

    // 256 threads over 1024 columns (4 each), L2 reads (bypass possibly-stale L1)
    float acc = 0.f;
    #pragma unroll
    for (int m = 0; m < 4; m++) {
        int j  = tid + m * 256;
        float S2 = __ldcg(&g_part[0][j]);
        float S1 = __ldcg(&g_part[1][j]);
        float SX = __ldcg(&g_part[2][j]);
        float n  = fmaxf(sqrtf(S2), 1e-12f);
        acc += (SX * LN2 - S1 * logf(n)) / n;
    }

    // re-zero scratch for the next graph replay
    for (int i = tid; i < 3 * COLS; i += 256) ((float*)g_part)[i] = 0.0f;
    if (tid == 0) g_count = 0u;

    __shared__ float sm[256];
    sm[tid] = acc;
    __syncthreads();
    #pragma unroll
    for (int s = 128; s > 0; s >>= 1) {
        if (tid < s) sm[tid] += sm[tid + s];
        __syncthreads();
    }
    if (tid == 0) out[0] = -sm[0] / (float)rows;
}

extern "C" void kernel_launch(void* const* d_in, const int* in_sizes, int n_in,
                              void* d_out, int out_size) {
    const float* x = (const float*)d_in[0];
    int rows = in_sizes[0] / COLS;   // 65536
    dim3 grid(GRID_X, GRID_Y);
    el_fused_kernel<<<grid, 256>>>(x, (float*)d_out, rows);
}